// round 13
// baseline (speedup 1.0000x reference)
#include <cuda_runtime.h>
#include <math.h>

#define Hh 2048
#define Wd 2048
#define MASKM 2047
#define Kk 16
#define Pp 15
#define TSTRIDE 144          // gather halo tile row stride (floats)
#define TILE_FLOATS (48 * TSTRIDE)   // 6912: one tile copy

// scratch (static device globals — no allocation)
__device__ float g_win[Hh * Wd];
__device__ float g_C;
__device__ int   g_nf;          // live fast entries (<= 16)
__device__ int   g_dfast[Kk];   // per-tap float-index deltas (A/B-parity folded)
__device__ float g_wfast[Kk];   // weights premultiplied by 1/3375
__device__ int   g_ng;          // out-of-range shifts (never in practice)
__device__ int   g_gsy[Kk], g_gsx[Kk];
__device__ float g_gw[Kk];      // premultiplied by 1/3375

// ---------------------------------------------------------------------------
// Kernel 1: fused separable 15x15 box-sum (zero-padded above/left).
// (R12-proven; only the prep's delta encoding changed for the dual-parity
// gather tile: odd-sx taps point into the shifted B copy.)
// ---------------------------------------------------------------------------
__global__ void __launch_bounds__(512)
k_box(const float* __restrict__ img,
      const float* __restrict__ patterns,
      const float* __restrict__ vectors) {
    __shared__ float rs[143 * 65];

    int t = threadIdx.x;
    int j0 = blockIdx.x * 64;
    int i0 = blockIdx.y * 128;

    // ---- prep (block (0,0) only) ----
    if (blockIdx.x == 0 && blockIdx.y == 0) {
        __shared__ float red[512];
        __shared__ int shy[Kk], shx[Kk];
        __shared__ int srare, sfast;
        const float scale = 1.0f / 3375.0f;

        if (t == 0) { srare = 0; sfast = 0; }
        if (t < Kk) {
            float vy = __ldg(vectors + 2 * t);
            float vx = __ldg(vectors + 2 * t + 1);
            int ny = ((int)floorf(vy)) & MASKM; if (ny >= 1024) ny -= 2048;
            int nx = ((int)floorf(vx)) & MASKM; if (nx >= 1024) nx -= 2048;
            shy[t] = ny; shx[t] = nx;
        }
        float s = 0.f;
        for (int i = t; i < 900; i += 512) {   // 3600 floats = 900 float4
            float4 f = __ldg((const float4*)patterns + i);
            s += f.x + f.y + f.z + f.w;
        }
        red[t] = s;
        __syncthreads();
        for (int off = 256; off > 0; off >>= 1) {
            if (t < off) red[t] += red[t + off];
            __syncthreads();
        }
        if (t < Kk) { g_dfast[t] = 0; g_wfast[t] = 0.f; }
        __syncthreads();
        if (t < Kk) {
            int ny = shy[t], nx = shx[t];
            int cnt = 0, first = Kk;
            #pragma unroll
            for (int m = 0; m < Kk; m++) {
                bool eq = (shy[m] == ny) && (shx[m] == nx);
                cnt += eq ? 1 : 0;
                if (eq && m < first) first = m;
            }
            bool isfirst = (first == t);
            bool inr = (ny >= -8 && ny <= 8 && nx >= -8 && nx <= 8);
            if (isfirst && inr) {
                int idx = atomicAdd(&sfast, 1);   // pack live entries first
                int dd = -ny * TSTRIDE - nx;
                if (nx & 1) dd += TILE_FLOATS - 1;   // odd sx -> B copy
                g_dfast[idx] = dd;
                g_wfast[idx] = (float)cnt * scale;
            }
            if (isfirst && !inr) {
                int idx = atomicAdd(&srare, 1);
                g_gsy[idx] = ny; g_gsx[idx] = nx;
                g_gw[idx] = (float)cnt * scale;
            }
        }
        __syncthreads();
        if (t == 0) {
            g_ng = srare;
            g_nf = sfast;
            g_C = ((float)Kk - red[0] / (float)(Pp * Pp)) / (float)(Kk - 1);
        }
        __syncthreads();
    }

    // ---- phase 1: horizontal sliding sum, 16 outputs/thread ----
    for (int tt = t; tt < 143 * 4; tt += 512) {
        int r   = tt >> 2;
        int seg = tt & 3;
        int arow = i0 - 15 + r;
        int jb = j0 + seg * 16;
        float o[16];
        if (arow < 0) {
            #pragma unroll
            for (int c = 0; c < 16; c++) o[c] = 0.f;
        } else {
            const float* row = img + (size_t)arow * Wd;
            float v[32];
            if (jb >= 16) {
                const float4* p = (const float4*)(row + jb - 16);
                #pragma unroll
                for (int q = 0; q < 8; q++) {
                    float4 f = __ldg(p + q);
                    v[4 * q + 0] = f.x; v[4 * q + 1] = f.y;
                    v[4 * q + 2] = f.z; v[4 * q + 3] = f.w;
                }
            } else {
                #pragma unroll
                for (int x = 0; x < 32; x++) {
                    int c = jb - 16 + x;
                    v[x] = (c >= 0) ? __ldg(row + c) : 0.f;
                }
            }
            float s = 0.f;
            #pragma unroll
            for (int x = 1; x <= 15; x++) s += v[x];
            o[0] = s;
            #pragma unroll
            for (int c = 1; c < 16; c++) { s += v[15 + c] - v[c]; o[c] = s; }
        }
        float* dst = rs + r * 65 + seg * 16;
        #pragma unroll
        for (int c = 0; c < 16; c++) dst[c] = o[c];
    }
    __syncthreads();

    // ---- phase 2: vertical sliding sum -> win ----
    int col = t & 63;
    int R0  = (t >> 6) * 16;
    const float* cp = rs + col;
    float s = 0.f;
    #pragma unroll
    for (int r = 0; r < 15; r++) s += cp[(R0 + r) * 65];
    float* outp = g_win + (size_t)(i0 + R0) * Wd + j0 + col;
    #pragma unroll
    for (int rr = 0; rr < 16; rr++) {
        outp[(size_t)rr * Wd] = s;
        if (rr < 15)
            s += cp[(R0 + rr + 15) * 65] - cp[(R0 + rr) * 65];
    }
}

// ---------------------------------------------------------------------------
// Kernel 2: out[i,j] = C + sum_m w'_m * win[(i-sy)&M][(j-sx)&M]
// Dual-parity tile: A = win halo 48x144; B[u][k] = A[u][k+1] (one-float
// shift) so odd-sx taps read 8B-aligned float2 from B. Each thread owns a
// column PAIR x 4 rows -> each tap is ONE LDS.64 serving 2 outputs:
// main-loop LDS instruction count halves vs R12.
// 32x128 tile/block, 512 threads, smem 55.5KB (4 blocks/SM, regs 32).
// grid = (16, 64).
// ---------------------------------------------------------------------------
#define GATHER_LOOP(NM)                                        \
    _Pragma("unroll")                                          \
    for (int m = 0; m < (NM); m++) {                           \
        float w = sw[m];                                       \
        const float2* p = (const float2*)(baseA + sd[m]);      \
        _Pragma("unroll")                                      \
        for (int rr = 0; rr < 4; rr++) {                       \
            float2 v = p[rr * (TSTRIDE / 2)];                  \
            acc[rr].x += w * v.x;                              \
            acc[rr].y += w * v.y;                              \
        }                                                      \
    }

__global__ void __launch_bounds__(512, 4) k_gather(float* __restrict__ out) {
    __shared__ float tile[2 * TILE_FLOATS];   // [A: 48x144][B: shifted copy]
    __shared__ int   sd[Kk];
    __shared__ float sw[Kk];
    __shared__ int   sng, snf;
    __shared__ float sC;

    int t = threadIdx.x;
    int j0 = blockIdx.x * 128;
    int i0 = blockIdx.y * 32;

    if (t < Kk) { sd[t] = g_dfast[t]; sw[t] = g_wfast[t]; }
    if (t == 0) { sng = g_ng; snf = g_nf; sC = g_C; }

    // stage A (48x144 halo, float4) and scatter the B copy (B[k]=A[k+1]).
    for (int idx = t; idx < 48 * 36; idx += 512) {
        int u  = idx / 36;
        int vq = idx - u * 36;
        int gr = (i0 - 8 + u) & MASKM;
        int gc = (j0 - 8 + 4 * vq) & MASKM;
        float4 f = __ldg((const float4*)(g_win + (size_t)gr * Wd + gc));
        float* arow = tile + u * TSTRIDE;
        *(float4*)(arow + 4 * vq) = f;
        float* brow = arow + TILE_FLOATS;
        int k = 4 * vq;
        if (k > 0) brow[k - 1] = f.x;   // B[k-1] = A[k]
        brow[k]     = f.y;              // B[k]   = A[k+1]
        brow[k + 1] = f.z;
        brow[k + 2] = f.w;              // B col 143 never read
    }
    __syncthreads();

    // thread -> column pair c (0..63) x row group g (0..7) of 4 rows
    int c  = t & 63;
    int g  = t >> 6;
    int R0 = 4 * g;
    const float* baseA = tile + (R0 + 8) * TSTRIDE + 8 + 2 * c;

    float2 acc[4];
    #pragma unroll
    for (int rr = 0; rr < 4; rr++) { acc[rr].x = 0.f; acc[rr].y = 0.f; }

    int nf = snf;
    if (nf <= 8)       { GATHER_LOOP(8)  }
    else if (nf <= 10) { GATHER_LOOP(10) }
    else if (nf <= 12) { GATHER_LOOP(12) }
    else if (nf <= 14) { GATHER_LOOP(14) }
    else               { GATHER_LOOP(16) }

    int ng = sng;
    if (ng > 0) {  // uniform, essentially never taken
        for (int m = 0; m < ng; m++) {
            int sy = g_gsy[m], sx = g_gsx[m];
            float w = g_gw[m];
            int jc0 = (j0 + 2 * c - sx) & MASKM;
            int jc1 = (j0 + 2 * c + 1 - sx) & MASKM;
            #pragma unroll 1
            for (int rr = 0; rr < 4; rr++) {
                int gr = (i0 + R0 + rr - sy) & MASKM;
                acc[rr].x += w * __ldg(g_win + (size_t)gr * Wd + jc0);
                acc[rr].y += w * __ldg(g_win + (size_t)gr * Wd + jc1);
            }
        }
    }

    float cb = sC;
    float* op = out + (size_t)(i0 + R0) * Wd + j0 + 2 * c;
    #pragma unroll
    for (int rr = 0; rr < 4; rr++) {
        float2 o2; o2.x = cb + acc[rr].x; o2.y = cb + acc[rr].y;
        *(float2*)(op + (size_t)rr * Wd) = o2;
    }
}

// ---------------------------------------------------------------------------
extern "C" void kernel_launch(void* const* d_in, const int* in_sizes, int n_in,
                              void* d_out, int out_size) {
    const float* x        = (const float*)d_in[0];  // (1,1,2048,2048)
    const float* patterns = (const float*)d_in[1];  // (16,15,15)
    const float* vectors  = (const float*)d_in[2];  // (16,2)
    float* out = (float*)d_out;                     // (2048,2048)

    k_box<<<dim3(32, 16), 512>>>(x, patterns, vectors);
    k_gather<<<dim3(16, 64), 512>>>(out);
}

// round 14
// speedup vs baseline: 1.1509x; 1.1509x over previous
#include <cuda_runtime.h>
#include <math.h>

#define Hh 2048
#define Wd 2048
#define MASKM 2047
#define Kk 16
#define Pp 15
#define TSTRIDE 144   // gather halo tile row stride

// scratch (static device globals — no allocation)
__device__ float g_win[Hh * Wd];
__device__ float g_C;
__device__ int   g_nf;          // number of live fast entries (<= 16)
__device__ int   g_dfast[Kk];   // smem-relative deltas (padded, w=0)
__device__ float g_wfast[Kk];   // weights premultiplied by 1/3375
__device__ int   g_ng;          // out-of-range shifts (never in practice)
__device__ int   g_gsy[Kk], g_gsx[Kk];
__device__ float g_gw[Kk];      // premultiplied by 1/3375

// ---------------------------------------------------------------------------
// Kernel 1: fused separable 15x15 box-sum (zero-padded above/left).
// win[i][j] = sum_{a=i-15..i-1, b=j-15..j-1} img[a][b]
// Tile: 128 rows x 64 cols per block; rowsum staged in SMEM (143 x 64,
// stride 65). grid = (32, 16), 512 threads. (R12-proven, unchanged.)
// Block (0,0) additionally does ALL prep work with fully-parallel dedupe.
// ---------------------------------------------------------------------------
__global__ void __launch_bounds__(512)
k_box(const float* __restrict__ img,
      const float* __restrict__ patterns,
      const float* __restrict__ vectors) {
    __shared__ float rs[143 * 65];

    int t = threadIdx.x;
    int j0 = blockIdx.x * 64;
    int i0 = blockIdx.y * 128;

    // ---- prep (block (0,0) only) ----
    if (blockIdx.x == 0 && blockIdx.y == 0) {
        __shared__ float red[512];
        __shared__ int shy[Kk], shx[Kk];
        __shared__ int srare, sfast;
        const float scale = 1.0f / 3375.0f;

        if (t == 0) { srare = 0; sfast = 0; }
        if (t < Kk) {
            float vy = __ldg(vectors + 2 * t);
            float vx = __ldg(vectors + 2 * t + 1);
            int ny = ((int)floorf(vy)) & MASKM; if (ny >= 1024) ny -= 2048;
            int nx = ((int)floorf(vx)) & MASKM; if (nx >= 1024) nx -= 2048;
            shy[t] = ny; shx[t] = nx;
        }
        float s = 0.f;
        for (int i = t; i < 900; i += 512) {   // 3600 floats = 900 float4
            float4 f = __ldg((const float4*)patterns + i);
            s += f.x + f.y + f.z + f.w;
        }
        red[t] = s;
        __syncthreads();
        for (int off = 256; off > 0; off >>= 1) {
            if (t < off) red[t] += red[t + off];
            __syncthreads();
        }
        if (t < Kk) { g_dfast[t] = 0; g_wfast[t] = 0.f; }
        __syncthreads();
        if (t < Kk) {
            int ny = shy[t], nx = shx[t];
            int cnt = 0, first = Kk;
            #pragma unroll
            for (int m = 0; m < Kk; m++) {
                bool eq = (shy[m] == ny) && (shx[m] == nx);
                cnt += eq ? 1 : 0;
                if (eq && m < first) first = m;
            }
            bool isfirst = (first == t);
            bool inr = (ny >= -8 && ny <= 8 && nx >= -8 && nx <= 8);
            if (isfirst && inr) {
                int idx = atomicAdd(&sfast, 1);   // pack live entries first
                g_dfast[idx] = -ny * TSTRIDE - nx;
                g_wfast[idx] = (float)cnt * scale;
            }
            if (isfirst && !inr) {
                int idx = atomicAdd(&srare, 1);
                g_gsy[idx] = ny; g_gsx[idx] = nx;
                g_gw[idx] = (float)cnt * scale;
            }
        }
        __syncthreads();
        if (t == 0) {
            g_ng = srare;
            g_nf = sfast;
            g_C = ((float)Kk - red[0] / (float)(Pp * Pp)) / (float)(Kk - 1);
        }
        __syncthreads();
    }

    // ---- phase 1: horizontal sliding sum, 16 outputs/thread ----
    for (int tt = t; tt < 143 * 4; tt += 512) {
        int r   = tt >> 2;
        int seg = tt & 3;
        int arow = i0 - 15 + r;
        int jb = j0 + seg * 16;
        float o[16];
        if (arow < 0) {
            #pragma unroll
            for (int c = 0; c < 16; c++) o[c] = 0.f;
        } else {
            const float* row = img + (size_t)arow * Wd;
            float v[32];
            if (jb >= 16) {
                const float4* p = (const float4*)(row + jb - 16);
                #pragma unroll
                for (int q = 0; q < 8; q++) {
                    float4 f = __ldg(p + q);
                    v[4 * q + 0] = f.x; v[4 * q + 1] = f.y;
                    v[4 * q + 2] = f.z; v[4 * q + 3] = f.w;
                }
            } else {
                #pragma unroll
                for (int x = 0; x < 32; x++) {
                    int c = jb - 16 + x;
                    v[x] = (c >= 0) ? __ldg(row + c) : 0.f;
                }
            }
            float s = 0.f;
            #pragma unroll
            for (int x = 1; x <= 15; x++) s += v[x];
            o[0] = s;
            #pragma unroll
            for (int c = 1; c < 16; c++) { s += v[15 + c] - v[c]; o[c] = s; }
        }
        float* dst = rs + r * 65 + seg * 16;
        #pragma unroll
        for (int c = 0; c < 16; c++) dst[c] = o[c];
    }
    __syncthreads();

    // ---- phase 2: vertical sliding sum -> win ----
    int col = t & 63;
    int R0  = (t >> 6) * 16;
    const float* cp = rs + col;
    float s = 0.f;
    #pragma unroll
    for (int r = 0; r < 15; r++) s += cp[(R0 + r) * 65];
    float* outp = g_win + (size_t)(i0 + R0) * Wd + j0 + col;
    #pragma unroll
    for (int rr = 0; rr < 16; rr++) {
        outp[(size_t)rr * Wd] = s;
        if (rr < 15)
            s += cp[(R0 + rr + 15) * 65] - cp[(R0 + rr) * 65];
    }
}

// ---------------------------------------------------------------------------
// Kernel 2: out[i,j] = C + sum_m w'_m * win[(i-sy)&M][(j-sx)&M]
// 32x128 tile/block, 512 threads (__launch_bounds__(512,4): 2048 thr/SM,
// regs=32 — R12-proven shape). 48x144 halo in SMEM (27.6KB).
// Finer nf-exact ladder (8/9/10/11/12/13/14/16): no wasted taps.
// grid = (16, 64); thread = 1 col x 8 rows (4 row-groups).
// ---------------------------------------------------------------------------
#define GATHER_LOOP(NM)                                        \
    _Pragma("unroll")                                          \
    for (int m = 0; m < (NM); m++) {                           \
        float w = sw[m];                                       \
        const float* p = base + sd[m];                         \
        _Pragma("unroll")                                      \
        for (int rr = 0; rr < 8; rr++)                         \
            acc[rr] += w * p[rr * TSTRIDE];                    \
    }

__global__ void __launch_bounds__(512, 4) k_gather(float* __restrict__ out) {
    __shared__ float tile[48 * TSTRIDE];
    __shared__ int   sd[Kk];
    __shared__ float sw[Kk];
    __shared__ int   sng, snf;
    __shared__ float sC;

    int t = threadIdx.x;
    int j0 = blockIdx.x * 128;
    int i0 = blockIdx.y * 32;

    if (t < Kk) { sd[t] = g_dfast[t]; sw[t] = g_wfast[t]; }
    if (t == 0) { sng = g_ng; snf = g_nf; sC = g_C; }

    // stage 48 x 144 halo via float4 (j0-8 ≡ 0 mod 4; wrap never splits)
    for (int idx = t; idx < 48 * 36; idx += 512) {
        int u  = idx / 36;
        int vq = idx - u * 36;
        int gr = (i0 - 8 + u) & MASKM;
        int gc = (j0 - 8 + 4 * vq) & MASKM;
        float4 f = __ldg((const float4*)(g_win + (size_t)gr * Wd + gc));
        *(float4*)&tile[u * TSTRIDE + 4 * vq] = f;
    }
    __syncthreads();

    int tx = t & 127;
    int R0 = (t >> 7) * 8;   // 0, 8, 16, 24
    const float* base = tile + (R0 + 8) * TSTRIDE + tx + 8;

    float acc[8];
    #pragma unroll
    for (int rr = 0; rr < 8; rr++) acc[rr] = 0.f;

    int nf = snf;
    if (nf <= 8)       { GATHER_LOOP(8)  }
    else if (nf == 9)  { GATHER_LOOP(9)  }
    else if (nf == 10) { GATHER_LOOP(10) }
    else if (nf == 11) { GATHER_LOOP(11) }
    else if (nf == 12) { GATHER_LOOP(12) }
    else if (nf == 13) { GATHER_LOOP(13) }
    else if (nf == 14) { GATHER_LOOP(14) }
    else               { GATHER_LOOP(16) }

    int ng = sng;
    if (ng > 0) {  // uniform, essentially never taken
        for (int m = 0; m < ng; m++) {
            int sy = g_gsy[m], sx = g_gsx[m];
            float w = g_gw[m];
            int gc = (j0 + tx - sx) & MASKM;
            #pragma unroll 1
            for (int rr = 0; rr < 8; rr++) {
                int gr = (i0 + R0 + rr - sy) & MASKM;
                acc[rr] += w * __ldg(g_win + (size_t)gr * Wd + gc);
            }
        }
    }

    float c = sC;
    float* op = out + (size_t)(i0 + R0) * Wd + j0 + tx;
    #pragma unroll
    for (int rr = 0; rr < 8; rr++)
        op[(size_t)rr * Wd] = c + acc[rr];
}

// ---------------------------------------------------------------------------
extern "C" void kernel_launch(void* const* d_in, const int* in_sizes, int n_in,
                              void* d_out, int out_size) {
    const float* x        = (const float*)d_in[0];  // (1,1,2048,2048)
    const float* patterns = (const float*)d_in[1];  // (16,15,15)
    const float* vectors  = (const float*)d_in[2];  // (16,2)
    float* out = (float*)d_out;                     // (2048,2048)

    k_box<<<dim3(32, 16), 512>>>(x, patterns, vectors);
    k_gather<<<dim3(16, 64), 512>>>(out);
}